// round 11
// baseline (speedup 1.0000x reference)
#include <cuda_runtime.h>
#include <cuda_fp16.h>

#define NN 1024
#define DIM 128
#define HH 4
#define I_TILE 8
#define LOG2E 1.4426950408889634f

typedef unsigned long long u64;
typedef unsigned int u32;

// Scratch (device globals: no allocations allowed)
__device__ __half g_Lh[NN * DIM];          // fp16 L, row-major [i][head*32+d]
__device__ __half g_Rh[NN * DIM];          // fp16 R, [head*4+qg][j][8 halves]
__device__ float  g_Vp[NN * DIM];          // paired: [head][j/2][d][2]
__device__ float  g_La6[NN * HH];          // 0.6*log2e * sum_d a_d*L (exp2-ready)
__device__ float  g_Ra6[NN * HH];
__device__ unsigned char g_adj8[128 * NN]; // byte per (i-block, j): bit ii = adj

#define FMA2(acc, p, v) \
    asm("fma.rn.f32x2 %0, %1, %2, %0;" : "+l"(acc) : "l"(p), "l"(v))
#define UNPACK2(lo, hi, s) \
    asm("mov.b64 {%0, %1}, %2;" : "=f"(lo), "=f"(hi) : "l"(s))
#define HADD2(d, x, y) \
    asm("add.rn.f16x2 %0, %1, %2;" : "=r"(d) : "r"(x), "r"(y))
#define HFMA2(acc, m, x) \
    asm("fma.rn.f16x2 %0, %1, %2, %0;" : "+r"(acc) : "r"(m), "r"(x))

// ---------------------------------------------------------------------------
// Prep: y=0: Lh = fp16(h@W_l); y=1: Rh = fp16 transposed h@W_r; y=2: Vp;
// plus La6/Ra6 (pre-scaled by 0.6*log2e). y=3: pack adj bits.
// Grid (128, 4), block 128. GEMM slices: 8 rows x 128 cols per CTA.
// ---------------------------------------------------------------------------
__global__ __launch_bounds__(128) void prep_kernel(
    const float* __restrict__ h,
    const int*   __restrict__ adj,
    const float* __restrict__ Wl,
    const float* __restrict__ Wr,
    const float* __restrict__ Wv,
    const float* __restrict__ a)
{
    int which = blockIdx.y;
    int tid = threadIdx.x;

    if (which == 3) {                    // adj bit-packing slice
        int i0 = blockIdx.x * 8;
#pragma unroll
        for (int jj = 0; jj < 8; jj++) {
            int j = tid + jj * 128;
            unsigned b = 0;
#pragma unroll
            for (int ii = 0; ii < 8; ii++)
                b |= (__ldg(&adj[(i0 + ii) * NN + j]) != 0 ? 1u : 0u) << ii;
            g_adj8[blockIdx.x * NN + j] = (unsigned char)b;
        }
        return;
    }

    const float* W = (which == 0) ? Wl : (which == 1) ? Wr : Wv;
    int i0 = blockIdx.x * 8;

    __shared__ float h_s[8 * DIM];
#pragma unroll
    for (int q = 0; q < 8; q++)
        h_s[tid + q * 128] = h[i0 * DIM + tid + q * 128];
    __syncthreads();

    float acc[8] = {0.f, 0.f, 0.f, 0.f, 0.f, 0.f, 0.f, 0.f};
    const float4* h4 = reinterpret_cast<const float4*>(h_s);
#pragma unroll 4
    for (int k4 = 0; k4 < 32; k4++) {
        float w0 = __ldg(&W[(k4 * 4 + 0) * DIM + tid]);
        float w1 = __ldg(&W[(k4 * 4 + 1) * DIM + tid]);
        float w2 = __ldg(&W[(k4 * 4 + 2) * DIM + tid]);
        float w3 = __ldg(&W[(k4 * 4 + 3) * DIM + tid]);
#pragma unroll
        for (int r = 0; r < 8; r++) {
            float4 hv = h4[r * 32 + k4];
            acc[r] += hv.x * w0 + hv.y * w1 + hv.z * w2 + hv.w * w3;
        }
    }

    int head = tid >> 5, d = tid & 31;
    if (which == 0) {
#pragma unroll
        for (int r = 0; r < 8; r++)
            g_Lh[(i0 + r) * DIM + tid] = __float2half_rn(acc[r]);
    } else if (which == 1) {
        // fp16 transposed: (j, head, d) -> g_Rh[((head*4+qg)*NN + j)*8 + slot]
        int qg = d >> 3, slot = d & 7;
        __half* base = &g_Rh[(size_t)((head * 4 + qg) * NN) * 8 + slot];
#pragma unroll
        for (int r = 0; r < 8; r++) base[(i0 + r) * 8] = __float2half_rn(acc[r]);
    } else {
        // paired store: {v[2k][d], v[2k+1][d]} at g_Vp[((head*512+k)*32+d)*2]
#pragma unroll
        for (int pr = 0; pr < 4; pr++) {
            float2 pv = make_float2(acc[2 * pr], acc[2 * pr + 1]);
            *reinterpret_cast<float2*>(
                &g_Vp[(size_t)((head * 512 + (i0 >> 1) + pr) * 32 + d) * 2]) = pv;
        }
    }

    if (which < 2) {
        float av = 0.6f * LOG2E * __ldg(&a[d]);
        float* A6 = (which == 0) ? g_La6 : g_Ra6;
#pragma unroll
        for (int r = 0; r < 8; r++) {
            float v = av * acc[r];
#pragma unroll
            for (int o = 16; o; o >>= 1) v += __shfl_xor_sync(0xffffffffu, v, o);
            if (d == 0) A6[(i0 + r) * HH + head] = v;
        }
    }
}

// ---------------------------------------------------------------------------
// Main fused kernel. Grid 128 (I_TILE=8 rows each), block 1024 = 32 warps
// (forces <=64 regs -> 32 warps/SM, 2x latency hiding vs 512-thread version).
// Warp w: head = w&3, jg = w>>2 (8 j-groups); per t (4 stages of 256 j) warp
// handles j = t*256 + jg*32 + lane, all 8 i-rows.
// e-phase fp16x2 (HADD2 + LOP abs + HFMA2); ar/la from smem (uniform
// broadcasts, frees 24 regs); agg f32x2 with just-in-time v loads.
// Max-free base-2 softmax; mask -> p = 0.
// ---------------------------------------------------------------------------
__global__ __launch_bounds__(1024, 1) void gat_main(
    const float* __restrict__ a,
    const float* __restrict__ ln_g,
    const float* __restrict__ ln_b,
    float*       __restrict__ out)
{
    __shared__ __align__(16) __half l_sh[I_TILE * DIM];    // fp16 l rows
    __shared__ __align__(16) float  p_s[32 * I_TILE * 32]; // [warp][ii][j] 32KB
    __shared__ __align__(16) float  o_s[I_TILE * DIM];     // final agg buffer
    __shared__ __align__(16) u32    ar_s[16];              // fp16x2 0.4*log2e*a
    __shared__ float la_s[I_TILE * HH];
    __shared__ float sl_s[32 * I_TILE];

    int tid  = threadIdx.x;
    int w    = tid >> 5, lane = tid & 31;
    int head = w & 3,    jg   = w >> 2;      // jg in 0..7
    int i0   = blockIdx.x * I_TILE;

    if (tid < 16) {
        __half2 hp = __floats2half2_rn((0.4f * LOG2E) * __ldg(&a[2 * tid]),
                                       (0.4f * LOG2E) * __ldg(&a[2 * tid + 1]));
        ar_s[tid] = *reinterpret_cast<u32*>(&hp);
    }
    if (tid < 128)       // stage fp16 l rows: 8 x 256B
        reinterpret_cast<uint4*>(l_sh)[tid] =
            __ldg(&reinterpret_cast<const uint4*>(g_Lh)[i0 * (DIM / 8) + tid]);
    if (tid < I_TILE * HH)
        la_s[tid] = __ldg(&g_La6[i0 * HH + tid]);

    float sl[I_TILE];
    u64 acc2[I_TILE];
#pragma unroll
    for (int ii = 0; ii < I_TILE; ii++) { sl[ii] = 0.f; acc2[ii] = 0ull; }
    __syncthreads();   // l_sh / ar_s / la_s visible

    const uint4*  Rh4 = reinterpret_cast<const uint4*>(g_Rh);
    const double* Vp  = reinterpret_cast<const double*>(g_Vp);
    float* myp = &p_s[w * I_TILE * 32];

    for (int t = 0; t < 4; t++) {
        int jcol = t * 256 + jg * 32 + lane;      // this lane's j
        int jpb  = head * 512 + t * 128 + jg * 16;// j-pair base for this warp

        // ---- stage-top loads: r (4x LDG.128 fp16), ra, adj ----
        uint4 r4[4];
#pragma unroll
        for (int qg = 0; qg < 4; qg++)
            r4[qg] = __ldg(&Rh4[(head * 4 + qg) * NN + jcol]);
        float ra = __ldg(&g_Ra6[jcol * HH + head]);
        unsigned b = __ldg(&g_adj8[blockIdx.x * NN + jcol]);

        // ---- e phase: fp16x2 HADD2 + abs(LOP) + HFMA2 ----
#pragma unroll
        for (int ii = 0; ii < I_TILE; ii++) {
            const uint4* lrow = reinterpret_cast<const uint4*>(&l_sh[ii * DIM + head * 32]);
            const uint4* arp  = reinterpret_cast<const uint4*>(ar_s);
            u32 ea0 = 0u, ea1 = 0u, ea2 = 0u, ea3 = 0u;   // half2 zeros
#pragma unroll
            for (int qg = 0; qg < 4; qg++) {
                uint4 l4 = lrow[qg];
                uint4 ar4 = arp[qg];
                u32 y0, y1, y2, y3;
                HADD2(y0, l4.x, r4[qg].x);
                HADD2(y1, l4.y, r4[qg].y);
                HADD2(y2, l4.z, r4[qg].z);
                HADD2(y3, l4.w, r4[qg].w);
                y0 &= 0x7FFF7FFFu; y1 &= 0x7FFF7FFFu;     // |.| both halves (ALU)
                y2 &= 0x7FFF7FFFu; y3 &= 0x7FFF7FFFu;
                HFMA2(ea0, ar4.x, y0);
                HFMA2(ea1, ar4.y, y1);
                HFMA2(ea2, ar4.z, y2);
                HFMA2(ea3, ar4.w, y3);
            }
            HADD2(ea0, ea0, ea1);
            HADD2(ea2, ea2, ea3);
            HADD2(ea0, ea0, ea2);
            float2 f2 = __half22float2(*reinterpret_cast<__half2*>(&ea0));
            float e = (la_s[ii * HH + head] + ra) + (f2.x + f2.y);
            float p;
            asm("ex2.approx.f32 %0, %1;" : "=f"(p) : "f"(e));
            p = (b & (1u << ii)) ? p : 0.f;
            sl[ii] += p;
            myp[ii * 32 + lane] = p;
        }
        __syncwarp();

        // ---- agg phase: lane owns d; just-in-time v (8 warps/SMSP hide it) ----
#pragma unroll
        for (int q4 = 0; q4 < 4; q4++) {
            const double* vp = &Vp[(size_t)(jpb + q4 * 4) * 32 + lane];
            u64 v0 = __double_as_longlong(__ldg(vp + 0 * 32));
            u64 v1 = __double_as_longlong(__ldg(vp + 1 * 32));
            u64 v2 = __double_as_longlong(__ldg(vp + 2 * 32));
            u64 v3 = __double_as_longlong(__ldg(vp + 3 * 32));
#pragma unroll
            for (int ii = 0; ii < I_TILE; ii++) {
                ulonglong2 pA = *reinterpret_cast<const ulonglong2*>(&myp[ii * 32 + q4 * 8]);
                ulonglong2 pB = *reinterpret_cast<const ulonglong2*>(&myp[ii * 32 + q4 * 8 + 4]);
                FMA2(acc2[ii], pA.x, v0);
                FMA2(acc2[ii], pA.y, v1);
                FMA2(acc2[ii], pB.x, v2);
                FMA2(acc2[ii], pB.y, v3);
            }
        }
        __syncwarp();
    }

    // ---- cross-warp (jg) reduction ----
#pragma unroll
    for (int ii = 0; ii < I_TILE; ii++) {
        float S = sl[ii];
#pragma unroll
        for (int o = 16; o; o >>= 1) S += __shfl_xor_sync(0xffffffffu, S, o);
        sl[ii] = S;
    }
    __syncthreads();                 // everyone done with p_s as p-buffer
#pragma unroll
    for (int ii = 0; ii < I_TILE; ii++) {
        float lo, hi;
        UNPACK2(lo, hi, acc2[ii]);
        myp[ii * 32 + lane] = lo + hi;           // reuse p_s as acc buffer
        if (lane == 0) sl_s[w * I_TILE + ii] = sl[ii];
    }
    __syncthreads();

    // warp w handles (hh = w&3, ii = w>>2): reduce over 8 jg groups
    {
        int hh = w & 3, ii = w >> 2;
        float acc = 0.f, S = 0.f;
#pragma unroll
        for (int g = 0; g < 8; g++) {
            acc += p_s[((g * 4 + hh) * I_TILE + ii) * 32 + lane];
            S   += sl_s[(g * 4 + hh) * I_TILE + ii];
        }
        o_s[ii * DIM + hh * 32 + lane] = acc * __frcp_rn(S);
    }
    __syncthreads();

    // LayerNorm + ReLU: warps 0..7 handle rows 0..7
    if (w < I_TILE) {
        int i = w;
        float v0 = o_s[i * DIM + lane];
        float v1 = o_s[i * DIM + 32 + lane];
        float v2 = o_s[i * DIM + 64 + lane];
        float v3 = o_s[i * DIM + 96 + lane];
        float sm = (v0 + v1) + (v2 + v3);
        float sq = v0 * v0 + v1 * v1 + v2 * v2 + v3 * v3;
#pragma unroll
        for (int o = 16; o; o >>= 1) {
            sm += __shfl_xor_sync(0xffffffffu, sm, o);
            sq += __shfl_xor_sync(0xffffffffu, sq, o);
        }
        float mean = sm * (1.f / 128.f);
        float var  = sq * (1.f / 128.f) - mean * mean;
        float rstd = rsqrtf(var + 1e-5f);
        float vals[4] = {v0, v1, v2, v3};
#pragma unroll
        for (int k = 0; k < 4; k++) {
            int c = 32 * k + lane;
            float y = (vals[k] - mean) * rstd * __ldg(&ln_g[c]) + __ldg(&ln_b[c]);
            out[(i0 + i) * DIM + c] = fmaxf(y, 0.f);
        }
    }
}

extern "C" void kernel_launch(void* const* d_in, const int* in_sizes, int n_in,
                              void* d_out, int out_size)
{
    const float* h   = (const float*)d_in[0];
    const int*   adj = (const int*)  d_in[1];
    const float* Wl  = (const float*)d_in[2];
    const float* Wr  = (const float*)d_in[3];
    const float* Wv  = (const float*)d_in[4];
    const float* a   = (const float*)d_in[5];
    const float* g   = (const float*)d_in[6];
    const float* b   = (const float*)d_in[7];

    prep_kernel<<<dim3(128, 4), 128>>>(h, adj, Wl, Wr, Wv, a);
    gat_main<<<NN / I_TILE, 1024>>>(a, g, b, (float*)d_out);
}

// round 12
// speedup vs baseline: 2.1713x; 2.1713x over previous
#include <cuda_runtime.h>
#include <cuda_fp16.h>

#define NN 1024
#define DIM 128
#define HH 4
#define I_TILE 8
#define LOG2E 1.4426950408889634f

typedef unsigned long long u64;
typedef unsigned int u32;

// Scratch (device globals: no allocations allowed)
__device__ __half g_Lh[NN * DIM];          // fp16 L, row-major [i][head*32+d]
__device__ __half g_Rh[NN * DIM];          // fp16 R, [head*4+qg][j][8 halves]
__device__ u32    g_Vf[NN * DIM / 2];      // fp16 V in HMMA B-fragment order:
                                           // [head][jb(64)][dt(4)][lane(32)][2]
__device__ float  g_La6[NN * HH];          // 0.6*log2e * sum_d a_d*L (exp2-ready)
__device__ float  g_Ra6[NN * HH];
__device__ unsigned char g_adj8[128 * NN]; // byte per (i-block, j): bit ii = adj

#define HADD2(d, x, y) \
    asm("add.rn.f16x2 %0, %1, %2;" : "=r"(d) : "r"(x), "r"(y))
#define HFMA2(acc, m, x) \
    asm("fma.rn.f16x2 %0, %1, %2, %0;" : "+r"(acc) : "r"(m), "r"(x))
#define MMA16816(d0, d1, d2, d3, a0, a1, a2, a3, b0, b1) \
    asm volatile("mma.sync.aligned.m16n8k16.row.col.f32.f16.f16.f32 " \
                 "{%0,%1,%2,%3}, {%4,%5,%6,%7}, {%8,%9}, {%0,%1,%2,%3};" \
                 : "+f"(d0), "+f"(d1), "+f"(d2), "+f"(d3) \
                 : "r"(a0), "r"(a1), "r"(a2), "r"(a3), "r"(b0), "r"(b1))

// ---------------------------------------------------------------------------
// Prep: y=0: Lh = fp16(h@W_l); y=1: Rh = fp16 transposed h@W_r;
// y=2: Vf = fp16 h@W_v stored in mma.m16n8k16 B-fragment order;
// plus La6/Ra6 (pre-scaled by 0.6*log2e). y=3: pack adj bits.
// Grid (128, 4), block 128. GEMM slices: 8 rows x 128 cols per CTA.
// ---------------------------------------------------------------------------
__global__ __launch_bounds__(128) void prep_kernel(
    const float* __restrict__ h,
    const int*   __restrict__ adj,
    const float* __restrict__ Wl,
    const float* __restrict__ Wr,
    const float* __restrict__ Wv,
    const float* __restrict__ a)
{
    int which = blockIdx.y;
    int tid = threadIdx.x;

    if (which == 3) {                    // adj bit-packing slice
        int i0 = blockIdx.x * 8;
#pragma unroll
        for (int jj = 0; jj < 8; jj++) {
            int j = tid + jj * 128;
            unsigned b = 0;
#pragma unroll
            for (int ii = 0; ii < 8; ii++)
                b |= (__ldg(&adj[(i0 + ii) * NN + j]) != 0 ? 1u : 0u) << ii;
            g_adj8[blockIdx.x * NN + j] = (unsigned char)b;
        }
        return;
    }

    const float* W = (which == 0) ? Wl : (which == 1) ? Wr : Wv;
    int i0 = blockIdx.x * 8;

    __shared__ float h_s[8 * DIM];
#pragma unroll
    for (int q = 0; q < 8; q++)
        h_s[tid + q * 128] = h[i0 * DIM + tid + q * 128];
    __syncthreads();

    float acc[8] = {0.f, 0.f, 0.f, 0.f, 0.f, 0.f, 0.f, 0.f};
    const float4* h4 = reinterpret_cast<const float4*>(h_s);
#pragma unroll 4
    for (int k4 = 0; k4 < 32; k4++) {
        float w0 = __ldg(&W[(k4 * 4 + 0) * DIM + tid]);
        float w1 = __ldg(&W[(k4 * 4 + 1) * DIM + tid]);
        float w2 = __ldg(&W[(k4 * 4 + 2) * DIM + tid]);
        float w3 = __ldg(&W[(k4 * 4 + 3) * DIM + tid]);
#pragma unroll
        for (int r = 0; r < 8; r++) {
            float4 hv = h4[r * 32 + k4];
            acc[r] += hv.x * w0 + hv.y * w1 + hv.z * w2 + hv.w * w3;
        }
    }

    int head = tid >> 5, d = tid & 31;
    if (which == 0) {
#pragma unroll
        for (int r = 0; r < 8; r++)
            g_Lh[(i0 + r) * DIM + tid] = __float2half_rn(acc[r]);
    } else if (which == 1) {
        // fp16 transposed: (j, head, d) -> g_Rh[((head*4+qg)*NN + j)*8 + slot]
        int qg = d >> 3, slot = d & 7;
        __half* base = &g_Rh[(size_t)((head * 4 + qg) * NN) * 8 + slot];
#pragma unroll
        for (int r = 0; r < 8; r++) base[(i0 + r) * 8] = __float2half_rn(acc[r]);
    } else {
        // B-fragment store. This CTA's rows = j k-range [regsel*8, regsel*8+8)
        // of j-block jb. lane l = 4n + m holds {V[2m(+8)][n], V[2m+1(+8)][n]}.
        int dt = d >> 3, n = d & 7;
        int jb = blockIdx.x >> 1, regsel = blockIdx.x & 1;
        u32 base = (((head * 64 + jb) * 4 + dt) * 32 + 4 * n) * 2 + regsel;
#pragma unroll
        for (int m = 0; m < 4; m++) {
            __half2 hp = __floats2half2_rn(acc[2 * m], acc[2 * m + 1]);
            g_Vf[base + m * 2] = *reinterpret_cast<u32*>(&hp);
        }
    }

    if (which < 2) {
        float av = 0.6f * LOG2E * __ldg(&a[d]);
        float* A6 = (which == 0) ? g_La6 : g_Ra6;
#pragma unroll
        for (int r = 0; r < 8; r++) {
            float v = av * acc[r];
#pragma unroll
            for (int o = 16; o; o >>= 1) v += __shfl_xor_sync(0xffffffffu, v, o);
            if (d == 0) A6[(i0 + r) * HH + head] = v;
        }
    }
}

// ---------------------------------------------------------------------------
// Main fused kernel. Grid 128 (I_TILE=8 rows each), block 512 = 16 warps.
// Warp w: head = w&3, js = w>>2; per t handles j = t*128+js*32+lane, all 8 i.
// e-phase fp16x2 (HADD2 + LOP abs + HFMA2); p stored fp16 to smem.
// agg-phase on TENSOR pipe: ldmatrix A-frags (zero-row pads M 8->16) +
// fragment-ordered V from gmem + mma.m16n8k16 (fp32 accum).
// Max-free base-2 softmax; mask -> p = 0.
// ---------------------------------------------------------------------------
__global__ __launch_bounds__(512) void gat_main(
    const float* __restrict__ a,
    const float* __restrict__ ln_g,
    const float* __restrict__ ln_b,
    float*       __restrict__ out)
{
    __shared__ __align__(16) __half l_sh[I_TILE * DIM];       // fp16 l rows
    __shared__ __align__(16) __half p_sh[16 * I_TILE * 32 + 32]; // + zero row
    __shared__ __align__(16) float  red_s[16 * I_TILE * 32];  // cross-warp acc
    __shared__ __align__(16) float  o_s[I_TILE * DIM];
    __shared__ float sl_s[16 * I_TILE];

    int tid  = threadIdx.x;
    int w    = tid >> 5, lane = tid & 31;
    int head = w & 3,    js   = w >> 2;      // js in 0..3
    int i0   = blockIdx.x * I_TILE;

    // 0.4*log2e * a packed as 16 fp16x2 (d-pairs), warp-uniform in regs
    u32 ar2h[16];
#pragma unroll
    for (int s = 0; s < 16; s++) {
        __half2 hp = __floats2half2_rn((0.4f * LOG2E) * __ldg(&a[2 * s]),
                                       (0.4f * LOG2E) * __ldg(&a[2 * s + 1]));
        ar2h[s] = *reinterpret_cast<u32*>(&hp);
    }

    if (tid < 128)       // stage fp16 l rows: 8 x 256B
        reinterpret_cast<uint4*>(l_sh)[tid] =
            __ldg(&reinterpret_cast<const uint4*>(g_Lh)[i0 * (DIM / 8) + tid]);
    if (tid < 16)        // zero row for ldmatrix M-padding
        reinterpret_cast<u32*>(p_sh + 16 * 256)[tid] = 0u;

    float la[I_TILE], sl[I_TILE];
    float dacc[16];
#pragma unroll
    for (int ii = 0; ii < I_TILE; ii++) {
        la[ii] = __ldg(&g_La6[(i0 + ii) * HH + head]);
        sl[ii] = 0.f;
    }
#pragma unroll
    for (int k = 0; k < 16; k++) dacc[k] = 0.f;
    __syncthreads();   // l_sh + zero row visible

    const uint4* Rh4 = reinterpret_cast<const uint4*>(g_Rh);
    __half* myph = &p_sh[w * 256];
    int lg = lane >> 3, lr = lane & 7;       // ldmatrix tile group / row

    for (int t = 0; t < 8; t++) {
        int jcol = t * 128 + js * 32 + lane;      // this lane's j
        int jb0  = t * 8 + js * 2;                // first 16-j block

        // ---- stage-top loads: r, ra, adj, B-fragments (all L2 hits) ----
        uint4 r4[4];
#pragma unroll
        for (int qg = 0; qg < 4; qg++)
            r4[qg] = __ldg(&Rh4[(head * 4 + qg) * NN + jcol]);
        float ra = __ldg(&g_Ra6[jcol * HH + head]);
        unsigned b = __ldg(&g_adj8[blockIdx.x * NN + jcol]);
        uint2 bq[8];
#pragma unroll
        for (int ks = 0; ks < 2; ks++)
#pragma unroll
            for (int nt = 0; nt < 4; nt++)
                bq[ks * 4 + nt] = __ldg(reinterpret_cast<const uint2*>(
                    &g_Vf[(((head * 64 + jb0 + ks) * 4 + nt) * 32 + lane) * 2]));

        // ---- e phase: fp16x2 HADD2 + abs(LOP) + HFMA2 ----
#pragma unroll
        for (int ii = 0; ii < I_TILE; ii++) {
            const uint4* lrow = reinterpret_cast<const uint4*>(&l_sh[ii * DIM + head * 32]);
            u32 ea0 = 0u, ea1 = 0u, ea2 = 0u, ea3 = 0u;   // half2 zeros
#pragma unroll
            for (int qg = 0; qg < 4; qg++) {
                uint4 l4 = lrow[qg];
                u32 y0, y1, y2, y3;
                HADD2(y0, l4.x, r4[qg].x);
                HADD2(y1, l4.y, r4[qg].y);
                HADD2(y2, l4.z, r4[qg].z);
                HADD2(y3, l4.w, r4[qg].w);
                y0 &= 0x7FFF7FFFu; y1 &= 0x7FFF7FFFu;     // |.| both halves (ALU)
                y2 &= 0x7FFF7FFFu; y3 &= 0x7FFF7FFFu;
                HFMA2(ea0, ar2h[qg * 4 + 0], y0);
                HFMA2(ea1, ar2h[qg * 4 + 1], y1);
                HFMA2(ea2, ar2h[qg * 4 + 2], y2);
                HFMA2(ea3, ar2h[qg * 4 + 3], y3);
            }
            HADD2(ea0, ea0, ea1);
            HADD2(ea2, ea2, ea3);
            HADD2(ea0, ea0, ea2);
            float2 f2 = __half22float2(*reinterpret_cast<__half2*>(&ea0));
            float e = (la[ii] + ra) + (f2.x + f2.y);
            float p;
            asm("ex2.approx.f32 %0, %1;" : "=f"(p) : "f"(e));
            p = (b & (1u << ii)) ? p : 0.f;
            sl[ii] += p;
            myph[ii * 32 + lane] = __float2half_rn(p);
        }
        __syncwarp();

        // ---- agg phase on tensor pipe: ldmatrix + mma.m16n8k16 ----
#pragma unroll
        for (int ks = 0; ks < 2; ks++) {
            const __half* ap = (lg & 1) ? (p_sh + 16 * 256)
                                        : (myph + lr * 32 + ks * 16 + (lg >> 1) * 8);
            u32 sa = (u32)__cvta_generic_to_shared(ap);
            u32 a0, a1, a2, a3;
            asm volatile("ldmatrix.sync.aligned.m8n8.x4.shared.b16 {%0,%1,%2,%3}, [%4];"
                         : "=r"(a0), "=r"(a1), "=r"(a2), "=r"(a3) : "r"(sa));
#pragma unroll
            for (int nt = 0; nt < 4; nt++)
                MMA16816(dacc[nt * 4 + 0], dacc[nt * 4 + 1],
                         dacc[nt * 4 + 2], dacc[nt * 4 + 3],
                         a0, a1, a2, a3, bq[ks * 4 + nt].x, bq[ks * 4 + nt].y);
        }
        __syncwarp();   // LDSM consumed before next stage's STS overwrites p
    }

    // ---- cross-warp (js) reduction ----
#pragma unroll
    for (int ii = 0; ii < I_TILE; ii++) {
        float S = sl[ii];
#pragma unroll
        for (int o = 16; o; o >>= 1) S += __shfl_xor_sync(0xffffffffu, S, o);
        if (lane == 0) sl_s[w * I_TILE + ii] = S;
    }
    // write mma accumulators: lane holds (ii = lane/4, d = nt*8 + 2*(lane%4)+{0,1})
    {
        int iw = lane >> 2, db = 2 * (lane & 3);
        float* myred = &red_s[w * 256];
#pragma unroll
        for (int nt = 0; nt < 4; nt++) {
            myred[iw * 32 + nt * 8 + db]     = dacc[nt * 4 + 0];
            myred[iw * 32 + nt * 8 + db + 1] = dacc[nt * 4 + 1];
        }
    }
    __syncthreads();

    // warp w: head' = w&3, covers ii = (w>>2) and (w>>2)+4
#pragma unroll
    for (int r = 0; r < 2; r++) {
        int ii = (w >> 2) + r * 4;
        int hh = w & 3;
        float acc = 0.f, S = 0.f;
#pragma unroll
        for (int g = 0; g < 4; g++) {
            acc += red_s[((g * 4 + hh) * I_TILE + ii) * 32 + lane];
            S   += sl_s[(g * 4 + hh) * I_TILE + ii];
        }
        o_s[ii * DIM + hh * 32 + lane] = acc * __frcp_rn(S);
    }
    __syncthreads();

    // LayerNorm + ReLU: warps 0..7 handle rows 0..7
    if (w < I_TILE) {
        int i = w;
        float v0 = o_s[i * DIM + lane];
        float v1 = o_s[i * DIM + 32 + lane];
        float v2 = o_s[i * DIM + 64 + lane];
        float v3 = o_s[i * DIM + 96 + lane];
        float sm = (v0 + v1) + (v2 + v3);
        float sq = v0 * v0 + v1 * v1 + v2 * v2 + v3 * v3;
#pragma unroll
        for (int o = 16; o; o >>= 1) {
            sm += __shfl_xor_sync(0xffffffffu, sm, o);
            sq += __shfl_xor_sync(0xffffffffu, sq, o);
        }
        float mean = sm * (1.f / 128.f);
        float var  = sq * (1.f / 128.f) - mean * mean;
        float rstd = rsqrtf(var + 1e-5f);
        float vals[4] = {v0, v1, v2, v3};
#pragma unroll
        for (int k = 0; k < 4; k++) {
            int c = 32 * k + lane;
            float y = (vals[k] - mean) * rstd * __ldg(&ln_g[c]) + __ldg(&ln_b[c]);
            out[(i0 + i) * DIM + c] = fmaxf(y, 0.f);
        }
    }
}

extern "C" void kernel_launch(void* const* d_in, const int* in_sizes, int n_in,
                              void* d_out, int out_size)
{
    const float* h   = (const float*)d_in[0];
    const int*   adj = (const int*)  d_in[1];
    const float* Wl  = (const float*)d_in[2];
    const float* Wr  = (const float*)d_in[3];
    const float* Wv  = (const float*)d_in[4];
    const float* a   = (const float*)d_in[5];
    const float* g   = (const float*)d_in[6];
    const float* b   = (const float*)d_in[7];

    prep_kernel<<<dim3(128, 4), 128>>>(h, adj, Wl, Wr, Wv, a);
    gat_main<<<NN / I_TILE, 512>>>(a, g, b, (float*)d_out);
}